// round 8
// baseline (speedup 1.0000x reference)
#include <cuda_runtime.h>
#include <cuda_fp16.h>
#include <cstdint>

// ============================================================================
// Problem dims
// ============================================================================
static constexpr int NTOK = 8192;   // tokens (M)
static constexpr int KDIM = 4096;   // input dim  (a1*b1)
static constexpr int NDIM = 4096;   // output dim (a2*b2)

// Scratch (allocation-free rule: __device__ globals)
__device__ __half g_wt[(size_t)NDIM * KDIM];  // W^T: [n][k] fp16
__device__ __half g_xh[(size_t)NTOK * KDIM];  // x:   [m][k] fp16
__device__ float  g_at[64 * 64 * 64];         // at[j][r][i] = a[r,i,j]
__device__ float  g_bt[64 * 64 * 64];         // bt[l][r][k2] = b[r,k2,l]

// ============================================================================
// PTX helpers (sm_103 baseline only — NO tcgen05 / 'a' features)
// ============================================================================
__device__ __forceinline__ uint32_t smem_to_u32(const void* smem_ptr) {
    uint32_t addr;
    asm("{ .reg .u64 tmp; cvta.to.shared.u64 tmp, %1; cvt.u32.u64 %0, tmp; }"
        : "=r"(addr) : "l"(smem_ptr));
    return addr;
}

#define CP_ASYNC16(smem_u32, gptr) \
    asm volatile("cp.async.cg.shared.global [%0], [%1], 16;\n" \
                 :: "r"(smem_u32), "l"(gptr))
#define CP_COMMIT() asm volatile("cp.async.commit_group;\n" ::: "memory")
#define CP_WAIT(n)  asm volatile("cp.async.wait_group %0;\n" :: "n"(n) : "memory")

__device__ __forceinline__ void ldmx4(uint32_t* r, uint32_t addr) {
    asm volatile("ldmatrix.sync.aligned.m8n8.x4.shared.b16 {%0,%1,%2,%3}, [%4];"
                 : "=r"(r[0]), "=r"(r[1]), "=r"(r[2]), "=r"(r[3])
                 : "r"(addr));
}

__device__ __forceinline__ void mma16816(float* d, const uint32_t* a,
                                         uint32_t b0, uint32_t b1) {
    asm volatile(
        "mma.sync.aligned.m16n8k16.row.col.f32.f16.f16.f32 "
        "{%0,%1,%2,%3}, {%4,%5,%6,%7}, {%8,%9}, {%0,%1,%2,%3};"
        : "+f"(d[0]), "+f"(d[1]), "+f"(d[2]), "+f"(d[3])
        : "r"(a[0]), "r"(a[1]), "r"(a[2]), "r"(a[3]), "r"(b0), "r"(b1));
}

// 128B rows (64 halves = BK), 8 x 16B chunks.
// off(row, c) = row*128 + ((c ^ (row&7)) << 4)
// Key property: off(row, c) = off(row, 0) ^ (c << 4).
__device__ __forceinline__ uint32_t swz(uint32_t row, uint32_t c) {
    return row * 128u + (((c ^ (row & 7u)) & 7u) << 4);
}

// ============================================================================
// Kernel 0: transpose a -> at[j][r][i], b -> bt[l][r][k2]
// ============================================================================
__global__ void __launch_bounds__(256) transpose_ab_kernel(
    const float* __restrict__ a, const float* __restrict__ b)
{
    __shared__ float s[64 * 65];
    const int r = blockIdx.x & 63;
    const bool isA = blockIdx.x < 64;
    const float* src = (isA ? a : b) + (size_t)r * 4096;
    float* dst = isA ? g_at : g_bt;
    const int tid = threadIdx.x;

    #pragma unroll
    for (int idx = tid; idx < 4096; idx += 256)
        s[(idx >> 6) * 65 + (idx & 63)] = src[idx];
    __syncthreads();

    #pragma unroll
    for (int idx = tid; idx < 4096; idx += 256) {
        int j = idx >> 6, i = idx & 63;
        dst[(size_t)j * 4096 + r * 64 + i] = s[i * 65 + j];
    }
}

// ============================================================================
// Kernel 1: build W^T[n][k] in fp16 (4x4 register blocking).
// ============================================================================
__global__ void __launch_bounds__(256) build_wt_kernel()
{
    __shared__ float a_s[64 * 64];  // [r][i]
    __shared__ float b_s[64 * 64];  // [r][k2]
    const int n = blockIdx.x;
    const int j = n >> 6, l = n & 63;
    const int tid = threadIdx.x;

    const float* at_j = g_at + (size_t)j * 4096;
    const float* bt_l = g_bt + (size_t)l * 4096;
    #pragma unroll
    for (int idx = tid; idx < 4096; idx += 256) {
        a_s[idx] = at_j[idx];
        b_s[idx] = bt_l[idx];
    }
    __syncthreads();

    const int i0 = (tid >> 4) * 4;
    const int k0 = (tid & 15) * 4;

    float acc[4][4];
    #pragma unroll
    for (int ii = 0; ii < 4; ii++)
        #pragma unroll
        for (int kk = 0; kk < 4; kk++) acc[ii][kk] = 0.0f;

    #pragma unroll 4
    for (int r = 0; r < 64; r++) {
        float4 a4 = *reinterpret_cast<const float4*>(&a_s[r * 64 + i0]);
        float4 b4 = *reinterpret_cast<const float4*>(&b_s[r * 64 + k0]);
        const float av[4] = {a4.x, a4.y, a4.z, a4.w};
        const float bv[4] = {b4.x, b4.y, b4.z, b4.w};
        #pragma unroll
        for (int ii = 0; ii < 4; ii++)
            #pragma unroll
            for (int kk = 0; kk < 4; kk++)
                acc[ii][kk] = fmaf(av[ii], bv[kk], acc[ii][kk]);
    }

    #pragma unroll
    for (int ii = 0; ii < 4; ii++) {
        __half2 h0 = __floats2half2_rn(acc[ii][0], acc[ii][1]);
        __half2 h1 = __floats2half2_rn(acc[ii][2], acc[ii][3]);
        uint2 st;
        st.x = *reinterpret_cast<uint32_t*>(&h0);
        st.y = *reinterpret_cast<uint32_t*>(&h1);
        *reinterpret_cast<uint2*>(&g_wt[(size_t)n * KDIM + (i0 + ii) * 64 + k0]) = st;
    }
}

// ============================================================================
// Kernel 2: x fp32 -> fp16
// ============================================================================
__global__ void __launch_bounds__(256) convert_x_kernel(const float* __restrict__ x)
{
    const size_t total4 = (size_t)NTOK * KDIM / 4;
    size_t i = (size_t)blockIdx.x * blockDim.x + threadIdx.x;
    const size_t stride = (size_t)gridDim.x * blockDim.x;
    __half2* dst = reinterpret_cast<__half2*>(g_xh);
    for (; i < total4; i += stride) {
        float4 v = reinterpret_cast<const float4*>(x)[i];
        dst[2 * i + 0] = __floats2half2_rn(v.x, v.y);
        dst[2 * i + 1] = __floats2half2_rn(v.z, v.w);
    }
}

// ============================================================================
// Kernel 3: mma.sync fp16 GEMM
// Tile 128x128x64, 3 cp.async stages (96KB), 128 threads = 4 warps in 2x2,
// warp tile 64x64. Cross-iteration fragment pipelining: step-0 frags of
// iteration kb+1 are loaded during kb's last MMA group, right after the
// single per-kb CP_WAIT+barrier (which also publishes group kb+1).
// The tensor pipe never waits on LDSM at an iteration boundary.
// __launch_bounds__(128,2) -> 2 CTAs/SM.
// ============================================================================
static constexpr int BM = 128, BN = 128, BK = 64;
static constexpr int STAGES = 3;
static constexpr int A_STAGE = BM * BK * 2;   // 16384 B
static constexpr int B_STAGE = BN * BK * 2;   // 16384 B
static constexpr int GEMM_SMEM = STAGES * (A_STAGE + B_STAGE);  // 98304 B

__global__ void __launch_bounds__(128, 2) kron_gemm_kernel(
    float* __restrict__ out, const float* __restrict__ bias)
{
    extern __shared__ char smem[];
    const uint32_t smA = smem_to_u32(smem);
    const uint32_t smB = smA + STAGES * A_STAGE;

    const int tid  = threadIdx.x;
    const int wid  = tid >> 5;
    const int lane = tid & 31;
    const int wm   = wid & 1;   // 0..1 -> M (64 rows)
    const int wn   = wid >> 1;  // 0..1 -> N (64 cols)
    const int mBase = blockIdx.y * BM;
    const int nBase = blockIdx.x * BN;

    // cp.async: 128 rows x 8 chunks = 1024 chunks per operand; 8 per thread.
    const int c_row0 = tid >> 3;       // 0..15, strided by +16
    const int c_c    = tid & 7;

    const __half* Aptr = g_xh + ((size_t)mBase + c_row0) * KDIM + c_c * 8;
    const __half* Bptr = g_wt + ((size_t)nBase + c_row0) * KDIM + c_c * 8;
    const size_t rowStep = (size_t)16 * KDIM;

    uint32_t stOff[8];
    #pragma unroll
    for (int it = 0; it < 8; it++)
        stOff[it] = swz((uint32_t)(c_row0 + it * 16), (uint32_t)c_c);

    auto load_stage = [&](const __half* Ak, const __half* Bk, int slot) {
        uint32_t sA = smA + slot * A_STAGE;
        uint32_t sB = smB + slot * B_STAGE;
        #pragma unroll
        for (int it = 0; it < 8; it++)
            CP_ASYNC16(sA + stOff[it], Ak + it * rowStep);
        #pragma unroll
        for (int it = 0; it < 8; it++)
            CP_ASYNC16(sB + stOff[it], Bk + it * rowStep);
        CP_COMMIT();
    };

    float acc[4][8][4] = {};   // 128 regs

    const int lm_row = lane & 15;
    const int lm_hi  = lane >> 4;

    uint32_t baseA[4], baseB[4];
    #pragma unroll
    for (int mi = 0; mi < 4; mi++)
        baseA[mi] = swz((uint32_t)(wm * 64 + mi * 16 + lm_row), 0) ^ ((uint32_t)lm_hi << 4);
    #pragma unroll
    for (int ni = 0; ni < 4; ni++)
        baseB[ni] = swz((uint32_t)(wn * 64 + ni * 16 + lm_row), 0) ^ ((uint32_t)lm_hi << 4);

    uint32_t afrag[2][4][4];   // [ring][mi][reg]
    uint32_t bfrag[2][4][4];   // [ring][ni][reg]

    // load frags for k16-step s of the stage at slot `sl` into ring buf `buf`
    auto load_frags = [&](int sl, int s, int buf) {
        const uint32_t sA = smA + sl * A_STAGE;
        const uint32_t sB = smB + sl * B_STAGE;
        const uint32_t cx = (uint32_t)(2 * s) << 4;
        #pragma unroll
        for (int mi = 0; mi < 4; mi++) ldmx4(afrag[buf][mi], sA + (baseA[mi] ^ cx));
        #pragma unroll
        for (int ni = 0; ni < 4; ni++) ldmx4(bfrag[buf][ni], sB + (baseB[ni] ^ cx));
    };

    auto do_mmas = [&](int buf) {
        #pragma unroll
        for (int mi = 0; mi < 4; mi++) {
            #pragma unroll
            for (int nj = 0; nj < 8; nj++) {
                const uint32_t* bg = bfrag[buf][nj >> 1];
                uint32_t b0 = (nj & 1) ? bg[1] : bg[0];
                uint32_t b1 = (nj & 1) ? bg[3] : bg[2];
                mma16816(acc[mi][nj], afrag[buf][mi], b0, b1);
            }
        }
    };

    const int KITERS = KDIM / BK;     // 64

    // Prologue: stages 0,1 in flight; frags for (kb=0, step0) in buf0.
    load_stage(Aptr + 0 * BK, Bptr + 0 * BK, 0);   // group 0
    load_stage(Aptr + 1 * BK, Bptr + 1 * BK, 1);   // group 1
    CP_WAIT(1);            // group 0 complete (self)
    __syncthreads();       // publish group 0 across warps
    load_frags(0, 0, 0);

    int slot = 0, pslot = 2;
    #pragma unroll 1
    for (int kb = 0; kb < KITERS; kb++) {
        // Prefetch stage kb+2 into slot (kb+2)%3. Safe: the barrier at the
        // end of iter kb-1 guaranteed all warps finished reading this slot.
        const int kn = kb + STAGES - 1;
        if (kn < KITERS)
            load_stage(Aptr + kn * BK, Bptr + kn * BK, pslot);
        else
            CP_COMMIT();   // empty group keeps CP_WAIT(1) certifying kb+1

        // Steps 0..2: frag ring one step ahead within the stage.
        load_frags(slot, 1, 1);
        do_mmas(0);
        load_frags(slot, 2, 0);
        do_mmas(1);
        load_frags(slot, 3, 1);
        do_mmas(0);

        // Step 3: certify + publish group kb+1, cross-load next iteration's
        // step-0 frags (slot kb+1) into buf0, then issue step-3 MMAs (which
        // depend only on buf1) to cover the LDSM latency.
        if (kb + 1 < KITERS) {
            CP_WAIT(1);        // groups <= kb+1 complete (self)
            __syncthreads();   // publish; also closes slot kb for overwrite
            const int nslot = (slot == STAGES - 1) ? 0 : slot + 1;
            load_frags(nslot, 0, 0);
            do_mmas(1);
            slot = nslot;
            pslot = (pslot == STAGES - 1) ? 0 : pslot + 1;
        } else {
            do_mmas(1);
        }
    }

    // Epilogue
    const int gr = lane >> 2;
    const int gc = (lane & 3) * 2;
    float bv[8][2];
    #pragma unroll
    for (int nj = 0; nj < 8; nj++) {
        const int n0 = nBase + wn * 64 + nj * 8 + gc;
        bv[nj][0] = __ldg(&bias[n0]);
        bv[nj][1] = __ldg(&bias[n0 + 1]);
    }
    #pragma unroll
    for (int mi = 0; mi < 4; mi++) {
        const int m0 = mBase + wm * 64 + mi * 16 + gr;
        float* r0p = out + (size_t)m0 * NDIM;
        float* r1p = out + (size_t)(m0 + 8) * NDIM;
        #pragma unroll
        for (int nj = 0; nj < 8; nj++) {
            const int n0 = nBase + wn * 64 + nj * 8 + gc;
            float2 v0 = make_float2(acc[mi][nj][0] + bv[nj][0],
                                    acc[mi][nj][1] + bv[nj][1]);
            float2 v1 = make_float2(acc[mi][nj][2] + bv[nj][0],
                                    acc[mi][nj][3] + bv[nj][1]);
            *reinterpret_cast<float2*>(r0p + n0) = v0;
            *reinterpret_cast<float2*>(r1p + n0) = v1;
        }
    }
}

// ============================================================================
// kernel_launch
// ============================================================================
extern "C" void kernel_launch(void* const* d_in, const int* in_sizes, int n_in,
                              void* d_out, int out_size)
{
    const float* x    = (const float*)d_in[0];
    const float* a    = (const float*)d_in[1];
    const float* b    = (const float*)d_in[2];
    const float* bias = (const float*)d_in[3];
    float* out = (float*)d_out;

    static bool attr_set = false;
    if (!attr_set) {
        cudaFuncSetAttribute(kron_gemm_kernel,
                             cudaFuncAttributeMaxDynamicSharedMemorySize,
                             GEMM_SMEM);
        attr_set = true;
    }

    // 0. Transpose a, b into coalesced-read layouts
    transpose_ab_kernel<<<128, 256>>>(a, b);

    // 1. Materialize W^T in fp16 (register-blocked)
    build_wt_kernel<<<NDIM, 256>>>();

    // 2. Convert x to fp16
    convert_x_kernel<<<2048, 256>>>(x);

    // 3. Pipelined mma.sync fp16 GEMM with fused bias epilogue
    dim3 grid(NDIM / BN, NTOK / BM);   // (32, 64)
    kron_gemm_kernel<<<grid, 128, GEMM_SMEM>>>(out, bias);
}

// round 9
// speedup vs baseline: 1.3094x; 1.3094x over previous
#include <cuda_runtime.h>
#include <cuda_fp16.h>
#include <cstdint>

// ============================================================================
// Problem dims
// ============================================================================
static constexpr int NTOK = 8192;   // tokens (M)
static constexpr int KDIM = 4096;   // input dim  (a1*b1)
static constexpr int NDIM = 4096;   // output dim (a2*b2)

// Scratch (allocation-free rule: __device__ globals)
__device__ __half g_wt[(size_t)NDIM * KDIM];  // W^T: [n][k] fp16
__device__ __half g_xh[(size_t)NTOK * KDIM];  // x:   [m][k] fp16
__device__ float  g_at[64 * 64 * 64];         // at[j][r][i] = a[r,i,j]
__device__ float  g_bt[64 * 64 * 64];         // bt[l][r][k2] = b[r,k2,l]

// ============================================================================
// PTX helpers (sm_103 baseline only — NO tcgen05 / 'a' features)
// ============================================================================
__device__ __forceinline__ uint32_t smem_to_u32(const void* smem_ptr) {
    uint32_t addr;
    asm("{ .reg .u64 tmp; cvta.to.shared.u64 tmp, %1; cvt.u32.u64 %0, tmp; }"
        : "=r"(addr) : "l"(smem_ptr));
    return addr;
}

#define CP_ASYNC16(smem_u32, gptr) \
    asm volatile("cp.async.cg.shared.global [%0], [%1], 16;\n" \
                 :: "r"(smem_u32), "l"(gptr))
#define CP_COMMIT() asm volatile("cp.async.commit_group;\n" ::: "memory")
#define CP_WAIT(n)  asm volatile("cp.async.wait_group %0;\n" :: "n"(n) : "memory")

__device__ __forceinline__ void ldmx4(uint32_t* r, uint32_t addr) {
    asm volatile("ldmatrix.sync.aligned.m8n8.x4.shared.b16 {%0,%1,%2,%3}, [%4];"
                 : "=r"(r[0]), "=r"(r[1]), "=r"(r[2]), "=r"(r[3])
                 : "r"(addr));
}

__device__ __forceinline__ void mma16816(float* d, const uint32_t* a,
                                         uint32_t b0, uint32_t b1) {
    asm volatile(
        "mma.sync.aligned.m16n8k16.row.col.f32.f16.f16.f32 "
        "{%0,%1,%2,%3}, {%4,%5,%6,%7}, {%8,%9}, {%0,%1,%2,%3};"
        : "+f"(d[0]), "+f"(d[1]), "+f"(d[2]), "+f"(d[3])
        : "r"(a[0]), "r"(a[1]), "r"(a[2]), "r"(a[3]), "r"(b0), "r"(b1));
}

// 128B rows (64 halves = BK), 8 x 16B chunks.
// off(row, c) = row*128 + ((c ^ (row&7)) << 4)
// Key property: off(row, c) = off(row, 0) ^ (c << 4).
__device__ __forceinline__ uint32_t swz(uint32_t row, uint32_t c) {
    return row * 128u + (((c ^ (row & 7u)) & 7u) << 4);
}

// ============================================================================
// Kernel 0: transpose a -> at[j][r][i], b -> bt[l][r][k2]
// ============================================================================
__global__ void __launch_bounds__(256) transpose_ab_kernel(
    const float* __restrict__ a, const float* __restrict__ b)
{
    __shared__ float s[64 * 65];
    const int r = blockIdx.x & 63;
    const bool isA = blockIdx.x < 64;
    const float* src = (isA ? a : b) + (size_t)r * 4096;
    float* dst = isA ? g_at : g_bt;
    const int tid = threadIdx.x;

    #pragma unroll
    for (int idx = tid; idx < 4096; idx += 256)
        s[(idx >> 6) * 65 + (idx & 63)] = src[idx];
    __syncthreads();

    #pragma unroll
    for (int idx = tid; idx < 4096; idx += 256) {
        int j = idx >> 6, i = idx & 63;
        dst[(size_t)j * 4096 + r * 64 + i] = s[i * 65 + j];
    }
}

// ============================================================================
// Kernel 1: build W^T[n][k] in fp16 (4x4 register blocking).
// ============================================================================
__global__ void __launch_bounds__(256) build_wt_kernel()
{
    __shared__ float a_s[64 * 64];  // [r][i]
    __shared__ float b_s[64 * 64];  // [r][k2]
    const int n = blockIdx.x;
    const int j = n >> 6, l = n & 63;
    const int tid = threadIdx.x;

    const float* at_j = g_at + (size_t)j * 4096;
    const float* bt_l = g_bt + (size_t)l * 4096;
    #pragma unroll
    for (int idx = tid; idx < 4096; idx += 256) {
        a_s[idx] = at_j[idx];
        b_s[idx] = bt_l[idx];
    }
    __syncthreads();

    const int i0 = (tid >> 4) * 4;
    const int k0 = (tid & 15) * 4;

    float acc[4][4];
    #pragma unroll
    for (int ii = 0; ii < 4; ii++)
        #pragma unroll
        for (int kk = 0; kk < 4; kk++) acc[ii][kk] = 0.0f;

    #pragma unroll 4
    for (int r = 0; r < 64; r++) {
        float4 a4 = *reinterpret_cast<const float4*>(&a_s[r * 64 + i0]);
        float4 b4 = *reinterpret_cast<const float4*>(&b_s[r * 64 + k0]);
        const float av[4] = {a4.x, a4.y, a4.z, a4.w};
        const float bv[4] = {b4.x, b4.y, b4.z, b4.w};
        #pragma unroll
        for (int ii = 0; ii < 4; ii++)
            #pragma unroll
            for (int kk = 0; kk < 4; kk++)
                acc[ii][kk] = fmaf(av[ii], bv[kk], acc[ii][kk]);
    }

    #pragma unroll
    for (int ii = 0; ii < 4; ii++) {
        __half2 h0 = __floats2half2_rn(acc[ii][0], acc[ii][1]);
        __half2 h1 = __floats2half2_rn(acc[ii][2], acc[ii][3]);
        uint2 st;
        st.x = *reinterpret_cast<uint32_t*>(&h0);
        st.y = *reinterpret_cast<uint32_t*>(&h1);
        *reinterpret_cast<uint2*>(&g_wt[(size_t)n * KDIM + (i0 + ii) * 64 + k0]) = st;
    }
}

// ============================================================================
// Kernel 2: x fp32 -> fp16
// ============================================================================
__global__ void __launch_bounds__(256) convert_x_kernel(const float* __restrict__ x)
{
    const size_t total4 = (size_t)NTOK * KDIM / 4;
    size_t i = (size_t)blockIdx.x * blockDim.x + threadIdx.x;
    const size_t stride = (size_t)gridDim.x * blockDim.x;
    __half2* dst = reinterpret_cast<__half2*>(g_xh);
    for (; i < total4; i += stride) {
        float4 v = reinterpret_cast<const float4*>(x)[i];
        dst[2 * i + 0] = __floats2half2_rn(v.x, v.y);
        dst[2 * i + 1] = __floats2half2_rn(v.z, v.w);
    }
}

// ============================================================================
// Kernel 3: mma.sync fp16 GEMM  (restored R5 structure — measured 699.6us)
// Tile 128x128x64, 3 cp.async stages (96KB), 256 threads = 8 warps (4x2),
// warp tile 32x64. Register-ring pipeline over the 4 k16 steps per stage,
// bulk prefetch of stage kb+2 right after step-0 frag loads.
// __launch_bounds__(256,2) -> 2 CTAs/SM (16 warps/SM).
// ============================================================================
static constexpr int BM = 128, BN = 128, BK = 64;
static constexpr int STAGES = 3;
static constexpr int A_STAGE = BM * BK * 2;   // 16384 B
static constexpr int B_STAGE = BN * BK * 2;   // 16384 B
static constexpr int GEMM_SMEM = STAGES * (A_STAGE + B_STAGE);  // 98304 B

__global__ void __launch_bounds__(256, 2) kron_gemm_kernel(
    float* __restrict__ out, const float* __restrict__ bias)
{
    extern __shared__ char smem[];
    const uint32_t smA = smem_to_u32(smem);
    const uint32_t smB = smA + STAGES * A_STAGE;

    const int tid  = threadIdx.x;
    const int wid  = tid >> 5;
    const int lane = tid & 31;
    const int wm   = wid & 3;   // 0..3 -> M (32 rows)
    const int wn   = wid >> 2;  // 0..1 -> N (64 cols)
    const int mBase = blockIdx.y * BM;
    const int nBase = blockIdx.x * BN;

    // cp.async: 128 rows x 8 chunks = 1024 chunks per operand; 4 per thread.
    const int c_row0 = tid >> 3;       // 0..31, strided by +32
    const int c_c    = tid & 7;

    const __half* Aptr = g_xh + ((size_t)mBase + c_row0) * KDIM + c_c * 8;
    const __half* Bptr = g_wt + ((size_t)nBase + c_row0) * KDIM + c_c * 8;
    const size_t rowStep = (size_t)32 * KDIM;

    uint32_t stOff[4];
    #pragma unroll
    for (int it = 0; it < 4; it++)
        stOff[it] = swz((uint32_t)(c_row0 + it * 32), (uint32_t)c_c);

    auto load_stage = [&](const __half* Ak, const __half* Bk, int slot) {
        uint32_t sA = smA + slot * A_STAGE;
        uint32_t sB = smB + slot * B_STAGE;
        #pragma unroll
        for (int it = 0; it < 4; it++)
            CP_ASYNC16(sA + stOff[it], Ak + it * rowStep);
        #pragma unroll
        for (int it = 0; it < 4; it++)
            CP_ASYNC16(sB + stOff[it], Bk + it * rowStep);
        CP_COMMIT();
    };

    #pragma unroll
    for (int s = 0; s < STAGES - 1; s++)
        load_stage(Aptr + s * BK, Bptr + s * BK, s);

    float acc[2][8][4] = {};   // 64 regs

    const int lm_row = lane & 15;
    const int lm_hi  = lane >> 4;

    uint32_t baseA[2], baseB[4];
    #pragma unroll
    for (int mi = 0; mi < 2; mi++)
        baseA[mi] = swz((uint32_t)(wm * 32 + mi * 16 + lm_row), 0) ^ ((uint32_t)lm_hi << 4);
    #pragma unroll
    for (int ni = 0; ni < 4; ni++)
        baseB[ni] = swz((uint32_t)(wn * 64 + ni * 16 + lm_row), 0) ^ ((uint32_t)lm_hi << 4);

    uint32_t afrag[2][2][4];   // [ring][mi][reg]
    uint32_t bfrag[2][4][4];   // [ring][ni][reg]

    auto load_frags = [&](uint32_t sA, uint32_t sB, int s, int buf) {
        const uint32_t cx = (uint32_t)(2 * s) << 4;
        #pragma unroll
        for (int mi = 0; mi < 2; mi++) ldmx4(afrag[buf][mi], sA + (baseA[mi] ^ cx));
        #pragma unroll
        for (int ni = 0; ni < 4; ni++) ldmx4(bfrag[buf][ni], sB + (baseB[ni] ^ cx));
    };

    auto do_mmas = [&](int buf) {
        #pragma unroll
        for (int mi = 0; mi < 2; mi++) {
            #pragma unroll
            for (int nj = 0; nj < 8; nj++) {
                const uint32_t* bg = bfrag[buf][nj >> 1];
                uint32_t b0 = (nj & 1) ? bg[1] : bg[0];
                uint32_t b1 = (nj & 1) ? bg[3] : bg[2];
                mma16816(acc[mi][nj], afrag[buf][mi], b0, b1);
            }
        }
    };

    const int KITERS = KDIM / BK;     // 64
    int slot = 0, pslot = STAGES - 1;
    #pragma unroll 1
    for (int kb = 0; kb < KITERS; kb++) {
        CP_WAIT(1);
        __syncthreads();

        const uint32_t sA = smA + slot * A_STAGE;
        const uint32_t sB = smB + slot * B_STAGE;

        load_frags(sA, sB, 0, 0);

        // Bulk prefetch of stage kb+2 (slot freed by the barrier above).
        const int kn = kb + STAGES - 1;
        if (kn < KITERS)
            load_stage(Aptr + kn * BK, Bptr + kn * BK, pslot);
        else
            CP_COMMIT();   // keep group counting consistent

        #pragma unroll
        for (int s = 0; s < 4; s++) {
            if (s < 3) load_frags(sA, sB, s + 1, (s + 1) & 1);
            do_mmas(s & 1);
        }

        slot = (slot == STAGES - 1) ? 0 : slot + 1;
        pslot = (pslot == STAGES - 1) ? 0 : pslot + 1;
    }

    // Epilogue
    const int gr = lane >> 2;
    const int gc = (lane & 3) * 2;
    float bv[8][2];
    #pragma unroll
    for (int nj = 0; nj < 8; nj++) {
        const int n0 = nBase + wn * 64 + nj * 8 + gc;
        bv[nj][0] = __ldg(&bias[n0]);
        bv[nj][1] = __ldg(&bias[n0 + 1]);
    }
    #pragma unroll
    for (int mi = 0; mi < 2; mi++) {
        const int m0 = mBase + wm * 32 + mi * 16 + gr;
        float* r0p = out + (size_t)m0 * NDIM;
        float* r1p = out + (size_t)(m0 + 8) * NDIM;
        #pragma unroll
        for (int nj = 0; nj < 8; nj++) {
            const int n0 = nBase + wn * 64 + nj * 8 + gc;
            float2 v0 = make_float2(acc[mi][nj][0] + bv[nj][0],
                                    acc[mi][nj][1] + bv[nj][1]);
            float2 v1 = make_float2(acc[mi][nj][2] + bv[nj][0],
                                    acc[mi][nj][3] + bv[nj][1]);
            *reinterpret_cast<float2*>(r0p + n0) = v0;
            *reinterpret_cast<float2*>(r1p + n0) = v1;
        }
    }
}

// ============================================================================
// kernel_launch
// ============================================================================
extern "C" void kernel_launch(void* const* d_in, const int* in_sizes, int n_in,
                              void* d_out, int out_size)
{
    const float* x    = (const float*)d_in[0];
    const float* a    = (const float*)d_in[1];
    const float* b    = (const float*)d_in[2];
    const float* bias = (const float*)d_in[3];
    float* out = (float*)d_out;

    static bool attr_set = false;
    if (!attr_set) {
        cudaFuncSetAttribute(kron_gemm_kernel,
                             cudaFuncAttributeMaxDynamicSharedMemorySize,
                             GEMM_SMEM);
        attr_set = true;
    }

    // 0. Transpose a, b into coalesced-read layouts
    transpose_ab_kernel<<<128, 256>>>(a, b);

    // 1. Materialize W^T in fp16 (register-blocked)
    build_wt_kernel<<<NDIM, 256>>>();

    // 2. Convert x to fp16
    convert_x_kernel<<<2048, 256>>>(x);

    // 3. Pipelined mma.sync fp16 GEMM with fused bias epilogue
    dim3 grid(NDIM / BN, NTOK / BM);   // (32, 64)
    kron_gemm_kernel<<<grid, 256, GEMM_SMEM>>>(out, bias);
}

// round 10
// speedup vs baseline: 1.3105x; 1.0008x over previous
#include <cuda_runtime.h>
#include <cuda_fp16.h>
#include <cstdint>

// ============================================================================
// Problem dims
// ============================================================================
static constexpr int NTOK = 8192;   // tokens (M)
static constexpr int KDIM = 4096;   // input dim  (a1*b1)
static constexpr int NDIM = 4096;   // output dim (a2*b2)

// Scratch (allocation-free rule: __device__ globals)
__device__ __half g_wt[(size_t)NDIM * KDIM];  // W^T: [n][k] fp16
__device__ __half g_xh[(size_t)NTOK * KDIM];  // x:   [m][k] fp16
__device__ float  g_at[64 * 64 * 64];         // at[j][r][i] = a[r,i,j]
__device__ float  g_bt[64 * 64 * 64];         // bt[l][r][k2] = b[r,k2,l]

// ============================================================================
// PTX helpers (sm_103 baseline only — NO tcgen05 / 'a' features)
// ============================================================================
__device__ __forceinline__ uint32_t smem_to_u32(const void* smem_ptr) {
    uint32_t addr;
    asm("{ .reg .u64 tmp; cvta.to.shared.u64 tmp, %1; cvt.u32.u64 %0, tmp; }"
        : "=r"(addr) : "l"(smem_ptr));
    return addr;
}

#define CP_ASYNC16(smem_u32, gptr) \
    asm volatile("cp.async.cg.shared.global [%0], [%1], 16;\n" \
                 :: "r"(smem_u32), "l"(gptr))
#define CP_COMMIT() asm volatile("cp.async.commit_group;\n" ::: "memory")
#define CP_WAIT(n)  asm volatile("cp.async.wait_group %0;\n" :: "n"(n) : "memory")

__device__ __forceinline__ void ldmx4(uint32_t* r, uint32_t addr) {
    asm volatile("ldmatrix.sync.aligned.m8n8.x4.shared.b16 {%0,%1,%2,%3}, [%4];"
                 : "=r"(r[0]), "=r"(r[1]), "=r"(r[2]), "=r"(r[3])
                 : "r"(addr));
}

__device__ __forceinline__ void mma16816(float* d, const uint32_t* a,
                                         uint32_t b0, uint32_t b1) {
    asm volatile(
        "mma.sync.aligned.m16n8k16.row.col.f32.f16.f16.f32 "
        "{%0,%1,%2,%3}, {%4,%5,%6,%7}, {%8,%9}, {%0,%1,%2,%3};"
        : "+f"(d[0]), "+f"(d[1]), "+f"(d[2]), "+f"(d[3])
        : "r"(a[0]), "r"(a[1]), "r"(a[2]), "r"(a[3]), "r"(b0), "r"(b1));
}

// 128B rows (64 halves = BK), 8 x 16B chunks.
// off(row, c) = row*128 + ((c ^ (row&7)) << 4)
// Key property: off(row, c) = off(row, 0) ^ (c << 4).
__device__ __forceinline__ uint32_t swz(uint32_t row, uint32_t c) {
    return row * 128u + (((c ^ (row & 7u)) & 7u) << 4);
}

// ============================================================================
// Kernel 0: transpose a -> at[j][r][i], b -> bt[l][r][k2]
// ============================================================================
__global__ void __launch_bounds__(256) transpose_ab_kernel(
    const float* __restrict__ a, const float* __restrict__ b)
{
    __shared__ float s[64 * 65];
    const int r = blockIdx.x & 63;
    const bool isA = blockIdx.x < 64;
    const float* src = (isA ? a : b) + (size_t)r * 4096;
    float* dst = isA ? g_at : g_bt;
    const int tid = threadIdx.x;

    #pragma unroll
    for (int idx = tid; idx < 4096; idx += 256)
        s[(idx >> 6) * 65 + (idx & 63)] = src[idx];
    __syncthreads();

    #pragma unroll
    for (int idx = tid; idx < 4096; idx += 256) {
        int j = idx >> 6, i = idx & 63;
        dst[(size_t)j * 4096 + r * 64 + i] = s[i * 65 + j];
    }
}

// ============================================================================
// Kernel 1: build W^T[n][k] in fp16 (4x4 register blocking).
// ============================================================================
__global__ void __launch_bounds__(256) build_wt_kernel()
{
    __shared__ float a_s[64 * 64];  // [r][i]
    __shared__ float b_s[64 * 64];  // [r][k2]
    const int n = blockIdx.x;
    const int j = n >> 6, l = n & 63;
    const int tid = threadIdx.x;

    const float* at_j = g_at + (size_t)j * 4096;
    const float* bt_l = g_bt + (size_t)l * 4096;
    #pragma unroll
    for (int idx = tid; idx < 4096; idx += 256) {
        a_s[idx] = at_j[idx];
        b_s[idx] = bt_l[idx];
    }
    __syncthreads();

    const int i0 = (tid >> 4) * 4;
    const int k0 = (tid & 15) * 4;

    float acc[4][4];
    #pragma unroll
    for (int ii = 0; ii < 4; ii++)
        #pragma unroll
        for (int kk = 0; kk < 4; kk++) acc[ii][kk] = 0.0f;

    #pragma unroll 4
    for (int r = 0; r < 64; r++) {
        float4 a4 = *reinterpret_cast<const float4*>(&a_s[r * 64 + i0]);
        float4 b4 = *reinterpret_cast<const float4*>(&b_s[r * 64 + k0]);
        const float av[4] = {a4.x, a4.y, a4.z, a4.w};
        const float bv[4] = {b4.x, b4.y, b4.z, b4.w};
        #pragma unroll
        for (int ii = 0; ii < 4; ii++)
            #pragma unroll
            for (int kk = 0; kk < 4; kk++)
                acc[ii][kk] = fmaf(av[ii], bv[kk], acc[ii][kk]);
    }

    #pragma unroll
    for (int ii = 0; ii < 4; ii++) {
        __half2 h0 = __floats2half2_rn(acc[ii][0], acc[ii][1]);
        __half2 h1 = __floats2half2_rn(acc[ii][2], acc[ii][3]);
        uint2 st;
        st.x = *reinterpret_cast<uint32_t*>(&h0);
        st.y = *reinterpret_cast<uint32_t*>(&h1);
        *reinterpret_cast<uint2*>(&g_wt[(size_t)n * KDIM + (i0 + ii) * 64 + k0]) = st;
    }
}

// ============================================================================
// Kernel 2: x fp32 -> fp16
// ============================================================================
__global__ void __launch_bounds__(256) convert_x_kernel(const float* __restrict__ x)
{
    const size_t total4 = (size_t)NTOK * KDIM / 4;
    size_t i = (size_t)blockIdx.x * blockDim.x + threadIdx.x;
    const size_t stride = (size_t)gridDim.x * blockDim.x;
    __half2* dst = reinterpret_cast<__half2*>(g_xh);
    for (; i < total4; i += stride) {
        float4 v = reinterpret_cast<const float4*>(x)[i];
        dst[2 * i + 0] = __floats2half2_rn(v.x, v.y);
        dst[2 * i + 1] = __floats2half2_rn(v.z, v.w);
    }
}

// ============================================================================
// Kernel 3: mma.sync fp16 GEMM
// Tile 128x128x64, 3 cp.async stages (96KB), 256 threads = 8 warps (4x2),
// warp tile 32x64 (R5/R9 config, 64 acc regs). Cross-iteration fragment
// pipelining: the per-kb CP_WAIT+barrier sits before the LAST MMA group,
// and next iteration's step-0 frags are cross-loaded from the just-published
// slot while those MMAs run — no LDSM dependency at iteration boundaries.
// __launch_bounds__(256,2) -> 2 CTAs/SM (16 warps/SM).
// ============================================================================
static constexpr int BM = 128, BN = 128, BK = 64;
static constexpr int STAGES = 3;
static constexpr int A_STAGE = BM * BK * 2;   // 16384 B
static constexpr int B_STAGE = BN * BK * 2;   // 16384 B
static constexpr int GEMM_SMEM = STAGES * (A_STAGE + B_STAGE);  // 98304 B

__global__ void __launch_bounds__(256, 2) kron_gemm_kernel(
    float* __restrict__ out, const float* __restrict__ bias)
{
    extern __shared__ char smem[];
    const uint32_t smA = smem_to_u32(smem);
    const uint32_t smB = smA + STAGES * A_STAGE;

    const int tid  = threadIdx.x;
    const int wid  = tid >> 5;
    const int lane = tid & 31;
    const int wm   = wid & 3;   // 0..3 -> M (32 rows)
    const int wn   = wid >> 2;  // 0..1 -> N (64 cols)
    const int mBase = blockIdx.y * BM;
    const int nBase = blockIdx.x * BN;

    // cp.async: 128 rows x 8 chunks = 1024 chunks per operand; 4 per thread.
    const int c_row0 = tid >> 3;       // 0..31, strided by +32
    const int c_c    = tid & 7;

    const __half* Aptr = g_xh + ((size_t)mBase + c_row0) * KDIM + c_c * 8;
    const __half* Bptr = g_wt + ((size_t)nBase + c_row0) * KDIM + c_c * 8;
    const size_t rowStep = (size_t)32 * KDIM;

    uint32_t stOff[4];
    #pragma unroll
    for (int it = 0; it < 4; it++)
        stOff[it] = swz((uint32_t)(c_row0 + it * 32), (uint32_t)c_c);

    auto load_stage = [&](const __half* Ak, const __half* Bk, int slot) {
        uint32_t sA = smA + slot * A_STAGE;
        uint32_t sB = smB + slot * B_STAGE;
        #pragma unroll
        for (int it = 0; it < 4; it++)
            CP_ASYNC16(sA + stOff[it], Ak + it * rowStep);
        #pragma unroll
        for (int it = 0; it < 4; it++)
            CP_ASYNC16(sB + stOff[it], Bk + it * rowStep);
        CP_COMMIT();
    };

    float acc[2][8][4] = {};   // 64 regs

    const int lm_row = lane & 15;
    const int lm_hi  = lane >> 4;

    uint32_t baseA[2], baseB[4];
    #pragma unroll
    for (int mi = 0; mi < 2; mi++)
        baseA[mi] = swz((uint32_t)(wm * 32 + mi * 16 + lm_row), 0) ^ ((uint32_t)lm_hi << 4);
    #pragma unroll
    for (int ni = 0; ni < 4; ni++)
        baseB[ni] = swz((uint32_t)(wn * 64 + ni * 16 + lm_row), 0) ^ ((uint32_t)lm_hi << 4);

    uint32_t afrag[2][2][4];   // [ring][mi][reg]
    uint32_t bfrag[2][4][4];   // [ring][ni][reg]

    // Frags for k16-step s of the stage at slot sl -> ring buf `buf`.
    auto load_frags = [&](int sl, int s, int buf) {
        const uint32_t sA = smA + sl * A_STAGE;
        const uint32_t sB = smB + sl * B_STAGE;
        const uint32_t cx = (uint32_t)(2 * s) << 4;
        #pragma unroll
        for (int mi = 0; mi < 2; mi++) ldmx4(afrag[buf][mi], sA + (baseA[mi] ^ cx));
        #pragma unroll
        for (int ni = 0; ni < 4; ni++) ldmx4(bfrag[buf][ni], sB + (baseB[ni] ^ cx));
    };

    auto do_mmas = [&](int buf) {
        #pragma unroll
        for (int mi = 0; mi < 2; mi++) {
            #pragma unroll
            for (int nj = 0; nj < 8; nj++) {
                const uint32_t* bg = bfrag[buf][nj >> 1];
                uint32_t b0 = (nj & 1) ? bg[1] : bg[0];
                uint32_t b1 = (nj & 1) ? bg[3] : bg[2];
                mma16816(acc[mi][nj], afrag[buf][mi], b0, b1);
            }
        }
    };

    const int KITERS = KDIM / BK;     // 64

    // Prologue: stages 0,1 in flight; step-0 frags of kb=0 in buf0.
    load_stage(Aptr + 0 * BK, Bptr + 0 * BK, 0);   // group 0
    load_stage(Aptr + 1 * BK, Bptr + 1 * BK, 1);   // group 1
    CP_WAIT(1);            // group 0 complete
    __syncthreads();       // publish group 0
    load_frags(0, 0, 0);

    int slot = 0, pslot = 2;
    #pragma unroll 1
    for (int kb = 0; kb < KITERS; kb++) {
        // Prefetch stage kb+2 into slot (kb+2)%3 — freed by the barrier at
        // the end of the previous iteration.
        const int kn = kb + STAGES - 1;
        if (kn < KITERS)
            load_stage(Aptr + kn * BK, Bptr + kn * BK, pslot);
        else
            CP_COMMIT();   // empty group keeps CP_WAIT(1) certifying kb+1

        // Steps 0..2: intra-stage register ring, one step ahead.
        load_frags(slot, 1, 1);
        do_mmas(0);
        load_frags(slot, 2, 0);
        do_mmas(1);
        load_frags(slot, 3, 1);
        do_mmas(0);

        // Boundary: certify+publish group kb+1, cross-load next step-0 frags
        // into buf0, then run step-3 MMAs (depend only on buf1) over the LDSM.
        if (kb + 1 < KITERS) {
            CP_WAIT(1);
            __syncthreads();
            const int nslot = (slot == STAGES - 1) ? 0 : slot + 1;
            load_frags(nslot, 0, 0);
            do_mmas(1);
            slot = nslot;
            pslot = (pslot == STAGES - 1) ? 0 : pslot + 1;
        } else {
            do_mmas(1);
        }
    }

    // Epilogue
    const int gr = lane >> 2;
    const int gc = (lane & 3) * 2;
    float bv[8][2];
    #pragma unroll
    for (int nj = 0; nj < 8; nj++) {
        const int n0 = nBase + wn * 64 + nj * 8 + gc;
        bv[nj][0] = __ldg(&bias[n0]);
        bv[nj][1] = __ldg(&bias[n0 + 1]);
    }
    #pragma unroll
    for (int mi = 0; mi < 2; mi++) {
        const int m0 = mBase + wm * 32 + mi * 16 + gr;
        float* r0p = out + (size_t)m0 * NDIM;
        float* r1p = out + (size_t)(m0 + 8) * NDIM;
        #pragma unroll
        for (int nj = 0; nj < 8; nj++) {
            const int n0 = nBase + wn * 64 + nj * 8 + gc;
            float2 v0 = make_float2(acc[mi][nj][0] + bv[nj][0],
                                    acc[mi][nj][1] + bv[nj][1]);
            float2 v1 = make_float2(acc[mi][nj][2] + bv[nj][0],
                                    acc[mi][nj][3] + bv[nj][1]);
            *reinterpret_cast<float2*>(r0p + n0) = v0;
            *reinterpret_cast<float2*>(r1p + n0) = v1;
        }
    }
}

// ============================================================================
// kernel_launch
// ============================================================================
extern "C" void kernel_launch(void* const* d_in, const int* in_sizes, int n_in,
                              void* d_out, int out_size)
{
    const float* x    = (const float*)d_in[0];
    const float* a    = (const float*)d_in[1];
    const float* b    = (const float*)d_in[2];
    const float* bias = (const float*)d_in[3];
    float* out = (float*)d_out;

    static bool attr_set = false;
    if (!attr_set) {
        cudaFuncSetAttribute(kron_gemm_kernel,
                             cudaFuncAttributeMaxDynamicSharedMemorySize,
                             GEMM_SMEM);
        attr_set = true;
    }

    // 0. Transpose a, b into coalesced-read layouts
    transpose_ab_kernel<<<128, 256>>>(a, b);

    // 1. Materialize W^T in fp16 (register-blocked)
    build_wt_kernel<<<NDIM, 256>>>();

    // 2. Convert x to fp16
    convert_x_kernel<<<2048, 256>>>(x);

    // 3. Pipelined mma.sync fp16 GEMM with fused bias epilogue
    dim3 grid(NDIM / BN, NTOK / BM);   // (32, 64)
    kron_gemm_kernel<<<grid, 256, GEMM_SMEM>>>(out, bias);
}